// round 15
// baseline (speedup 1.0000x reference)
#include <cuda_runtime.h>
#include <cuda_fp16.h>

#define Nn 10000
#define Ee 160000
#define Cc 8
#define Bb 64
#define EPSv 1e-5f

// Scratch (device globals; allocation-free per harness rules)
__device__ __half g_xT16[Ee * Bb];     // x transposed+permuted, fp16
__device__ __half g_w1s16[Ee * Cc];    // w1 permuted, fp16 (16B per edge row)
__device__ __half g_h[Nn * Bb * Cc];   // LN+ELU activations, fp16, layout (N, B, C)
__device__ int    g_cnt[Nn];           // zero at module load; re-zeroed by scan_kernel each run
__device__ int    g_cursor[Nn];
__device__ int    g_start[Nn + 1];

// ---------------- packed f32x2 helpers (SASS FFMA2: 2 fp32 FMAs / issue slot) ----------------

__device__ __forceinline__ unsigned long long pack2(float lo, float hi) {
    unsigned long long r;
    asm("mov.b64 %0, {%1, %2};" : "=l"(r) : "f"(lo), "f"(hi));
    return r;
}
__device__ __forceinline__ void unpack2(float& lo, float& hi, unsigned long long v) {
    asm("mov.b64 {%0, %1}, %2;" : "=f"(lo), "=f"(hi) : "l"(v));
}
__device__ __forceinline__ void fma2(unsigned long long& d,
                                     unsigned long long a, unsigned long long b) {
    asm("fma.rn.f32x2 %0, %1, %2, %3;" : "=l"(d) : "l"(a), "l"(b), "l"(d));
}

// ---------------- histogram ----------------

__global__ void hist_kernel(const int* __restrict__ dst) {
    int e = blockIdx.x * blockDim.x + threadIdx.x;
    if (e < Ee) atomicAdd(&g_cnt[dst[e]], 1);
}

// Single-block exclusive scan over N=10000 counts; seeds g_cursor = g_start
// and ZEROES g_cnt for the next run (replaces the memset launch node).
__global__ void scan_kernel() {
    __shared__ int sh[1024];
    const int CH = (Nn + 1023) / 1024;  // 10
    int t = threadIdx.x;
    int base = t * CH;
    int loc[CH];
    int s = 0;
#pragma unroll
    for (int i = 0; i < CH; i++) {
        int v = 0;
        if (base + i < Nn) {
            v = g_cnt[base + i];
            g_cnt[base + i] = 0;         // restore zeros for the next invocation
        }
        loc[i] = s;
        s += v;
    }
    sh[t] = s;
    __syncthreads();
    for (int off = 1; off < 1024; off <<= 1) {
        int v = (t >= off) ? sh[t - off] : 0;
        __syncthreads();
        if (t >= off) sh[t] += v;
        __syncthreads();
    }
    int prev = (t > 0) ? sh[t - 1] : 0;
#pragma unroll
    for (int i = 0; i < CH; i++)
        if (base + i < Nn) {
            int v = prev + loc[i];
            g_start[base + i] = v;
            g_cursor[base + i] = v;
        }
    if (t == 1023) g_start[Nn] = sh[1023];
}

// ---------------- Fused rank-assign + transpose + permute (R11-exact) ----------------

__global__ void transpose_sort_kernel(const float* __restrict__ x,
                                      const int* __restrict__ dst,
                                      const float* __restrict__ w1) {
    __shared__ float tile[32][65];   // [e_local][b]
    __shared__ int ranks[32];
    int e0 = blockIdx.x * 32;
    int t = threadIdx.x;             // 256

    if (t < 32) {
        int d = dst[e0 + t];
        ranks[t] = atomicAdd(&g_cursor[d], 1);
    }

    int tx = t & 31, ty = t >> 5;    // tx = e_local, ty = 0..7
#pragma unroll
    for (int i = 0; i < 64; i += 8)
        tile[tx][ty + i] = x[(ty + i) * Ee + e0 + tx];
    __syncthreads();

    int b = t & 63, r = t >> 6;      // r = 0..3
#pragma unroll
    for (int i = 0; i < 32; i += 4)
        g_xT16[ranks[r + i] * Bb + b] = __float2half_rn(tile[r + i][b]);

    int er = t >> 3, c = t & 7;
    g_w1s16[ranks[er] * 8 + c] = __float2half_rn(w1[e0 * 8 + t]);
}

// ---------------- Fused scatter + bias + LayerNorm + ELU (R11-exact, measured best) ----------------
// 32 threads per node, 2 batch elements per thread; fp16 streams,
// packed f32x2 accumulation (FFMA2), full fp32 precision.

__global__ void scatter_ln_kernel(const float* __restrict__ b1,
                                  const float* __restrict__ gamma,
                                  const float* __restrict__ beta) {
    int node = blockIdx.x * 8 + (threadIdx.x >> 5);
    int l    = threadIdx.x & 31;      // lane; handles b = 2l, 2l+1
    if (node >= Nn) return;

    unsigned long long acc[8];
#pragma unroll
    for (int j = 0; j < 8; j++) acc[j] = pack2(0.0f, 0.0f);

    int s  = g_start[node];
    int se = g_start[node + 1];
    int i  = s;

    for (; i + 4 <= se; i += 4) {
        __half2 xh0 = *reinterpret_cast<const __half2*>(g_xT16 + (i + 0) * Bb + 2 * l);
        __half2 xh1 = *reinterpret_cast<const __half2*>(g_xT16 + (i + 1) * Bb + 2 * l);
        __half2 xh2 = *reinterpret_cast<const __half2*>(g_xT16 + (i + 2) * Bb + 2 * l);
        __half2 xh3 = *reinterpret_cast<const __half2*>(g_xT16 + (i + 3) * Bb + 2 * l);

#pragma unroll
        for (int k = 0; k < 4; k++) {
            float2 xf = __half22float2(k == 0 ? xh0 : (k == 1 ? xh1 : (k == 2 ? xh2 : xh3)));
            unsigned long long xp = pack2(xf.x, xf.y);
            uint4 wraw = *reinterpret_cast<const uint4*>(g_w1s16 + (i + k) * 8);
            const __half2* wp = reinterpret_cast<const __half2*>(&wraw);
            float2 w01 = __half22float2(wp[0]);
            float2 w23 = __half22float2(wp[1]);
            float2 w45 = __half22float2(wp[2]);
            float2 w67 = __half22float2(wp[3]);
            fma2(acc[0], xp, pack2(w01.x, w01.x));
            fma2(acc[1], xp, pack2(w01.y, w01.y));
            fma2(acc[2], xp, pack2(w23.x, w23.x));
            fma2(acc[3], xp, pack2(w23.y, w23.y));
            fma2(acc[4], xp, pack2(w45.x, w45.x));
            fma2(acc[5], xp, pack2(w45.y, w45.y));
            fma2(acc[6], xp, pack2(w67.x, w67.x));
            fma2(acc[7], xp, pack2(w67.y, w67.y));
        }
    }
    for (; i < se; i++) {
        __half2 xh = *reinterpret_cast<const __half2*>(g_xT16 + i * Bb + 2 * l);
        float2 xf = __half22float2(xh);
        unsigned long long xp = pack2(xf.x, xf.y);
        uint4 wraw = *reinterpret_cast<const uint4*>(g_w1s16 + i * 8);
        const __half2* wp = reinterpret_cast<const __half2*>(&wraw);
        float2 w01 = __half22float2(wp[0]);
        float2 w23 = __half22float2(wp[1]);
        float2 w45 = __half22float2(wp[2]);
        float2 w67 = __half22float2(wp[3]);
        fma2(acc[0], xp, pack2(w01.x, w01.x));
        fma2(acc[1], xp, pack2(w01.y, w01.y));
        fma2(acc[2], xp, pack2(w23.x, w23.x));
        fma2(acc[3], xp, pack2(w23.y, w23.y));
        fma2(acc[4], xp, pack2(w45.x, w45.x));
        fma2(acc[5], xp, pack2(w45.y, w45.y));
        fma2(acc[6], xp, pack2(w67.x, w67.x));
        fma2(acc[7], xp, pack2(w67.y, w67.y));
    }

    // unpack accumulators: a0 = batch 2l, a1 = batch 2l+1
    float a0[8], a1[8];
#pragma unroll
    for (int j = 0; j < 8; j++) unpack2(a0[j], a1[j], acc[j]);

    float4 c0 = *reinterpret_cast<const float4*>(b1 + node * 8);
    float4 c1 = *reinterpret_cast<const float4*>(b1 + node * 8 + 4);
    float cv[8] = {c0.x, c0.y, c0.z, c0.w, c1.x, c1.y, c1.z, c1.w};
#pragma unroll
    for (int j = 0; j < 8; j++) { a0[j] += cv[j]; a1[j] += cv[j]; }

    float4 ga = *reinterpret_cast<const float4*>(gamma + node * 8);
    float4 gb = *reinterpret_cast<const float4*>(gamma + node * 8 + 4);
    float4 ba = *reinterpret_cast<const float4*>(beta  + node * 8);
    float4 bb = *reinterpret_cast<const float4*>(beta  + node * 8 + 4);
    float gv[8] = {ga.x, ga.y, ga.z, ga.w, gb.x, gb.y, gb.z, gb.w};
    float bv[8] = {ba.x, ba.y, ba.z, ba.w, bb.x, bb.y, bb.z, bb.w};

    // LayerNorm + ELU per batch element (all registers)
    __half2 hp[8];
#pragma unroll
    for (int pass = 0; pass < 2; pass++) {
        float* a = pass ? a1 : a0;
        float mu = 0.0f;
#pragma unroll
        for (int j = 0; j < 8; j++) mu += a[j];
        mu *= 0.125f;
        float var = 0.0f;
#pragma unroll
        for (int j = 0; j < 8; j++) { float d = a[j] - mu; var = fmaf(d, d, var); }
        var *= 0.125f;
        float rr = rsqrtf(var + EPSv);
        float h[8];
#pragma unroll
        for (int j = 0; j < 8; j++) {
            float v = fmaf((a[j] - mu) * rr, gv[j], bv[j]);
            h[j] = (v > 0.0f) ? v : expm1f(v);
        }
#pragma unroll
        for (int j = 0; j < 4; j++)
            hp[pass * 4 + j] = __floats2half2_rn(h[2 * j], h[2 * j + 1]);
    }

    // two 16B stores: batches 2l and 2l+1
    uint4 o0, o1;
    o0.x = *reinterpret_cast<unsigned int*>(&hp[0]);
    o0.y = *reinterpret_cast<unsigned int*>(&hp[1]);
    o0.z = *reinterpret_cast<unsigned int*>(&hp[2]);
    o0.w = *reinterpret_cast<unsigned int*>(&hp[3]);
    o1.x = *reinterpret_cast<unsigned int*>(&hp[4]);
    o1.y = *reinterpret_cast<unsigned int*>(&hp[5]);
    o1.z = *reinterpret_cast<unsigned int*>(&hp[6]);
    o1.w = *reinterpret_cast<unsigned int*>(&hp[7]);
    __half* base = g_h + node * (Bb * Cc) + (2 * l) * Cc;
    *reinterpret_cast<uint4*>(base)     = o0;
    *reinterpret_cast<uint4*>(base + 8) = o1;
}

// ---------------- Fused gather + transpose + residual via smem staging (R11-exact) ----------------

#define GE 64  // edges per block

__global__ void gather_fused_kernel(const float* __restrict__ w3,
                                    const float* __restrict__ b3,
                                    const int* __restrict__ src,
                                    const float* __restrict__ x,
                                    float* __restrict__ out) {
    __shared__ float tile[Bb][GE + 1];
    int e0 = blockIdx.x * GE;
    int t = threadIdx.x;          // 256
    int b = t & 63;
    int g = t >> 6;               // 0..3

#pragma unroll 4
    for (int i = g; i < GE; i += 4) {
        int e = e0 + i;
        int sn = __ldg(src + e);                   // uniform within group
        uint4 raw = *reinterpret_cast<const uint4*>(g_h + sn * (Bb * Cc) + b * Cc);
        float2 f0 = __half22float2(*reinterpret_cast<__half2*>(&raw.x));
        float2 f1 = __half22float2(*reinterpret_cast<__half2*>(&raw.y));
        float2 f2 = __half22float2(*reinterpret_cast<__half2*>(&raw.z));
        float2 f3 = __half22float2(*reinterpret_cast<__half2*>(&raw.w));
        float4 wa = *reinterpret_cast<const float4*>(w3 + e * 8);
        float4 wb = *reinterpret_cast<const float4*>(w3 + e * 8 + 4);
        float sum = __ldg(b3 + e);
        sum = fmaf(f0.x, wa.x, sum);
        sum = fmaf(f0.y, wa.y, sum);
        sum = fmaf(f1.x, wa.z, sum);
        sum = fmaf(f1.y, wa.w, sum);
        sum = fmaf(f2.x, wb.x, sum);
        sum = fmaf(f2.y, wb.y, sum);
        sum = fmaf(f3.x, wb.z, sum);
        sum = fmaf(f3.y, wb.w, sum);
        tile[b][i] = sum;                          // stride-65: conflict-free
    }
    __syncthreads();

    int el = t & 63;
#pragma unroll
    for (int k = 0; k < 16; k++) {
        int b2 = (t >> 6) + k * 4;
        int idx = b2 * Ee + e0 + el;
        __stcs(&out[idx], tile[b2][el] + x[idx]);
    }
}

// ---------------- Launch ----------------

extern "C" void kernel_launch(void* const* d_in, const int* in_sizes, int n_in,
                              void* d_out, int out_size) {
    const float* x     = (const float*)d_in[0];   // (B,E)
    const float* w1    = (const float*)d_in[1];   // (E,C)
    const float* b1    = (const float*)d_in[2];   // (N,C)
    const float* gamma = (const float*)d_in[3];   // (N,C)
    const float* beta  = (const float*)d_in[4];   // (N,C)
    const float* w3    = (const float*)d_in[5];   // (E,C)
    const float* b3    = (const float*)d_in[6];   // (E,)
    const int* edge_src = (const int*)d_in[7];    // (E,)
    const int* edge_dst = (const int*)d_in[8];    // (E,)
    float* out = (float*)d_out;                   // (B,E)

    // g_cnt is zero at module load and re-zeroed by scan_kernel each run
    // (deterministic across graph replays; no memset node needed).
    hist_kernel<<<(Ee + 255) / 256, 256>>>(edge_dst);
    scan_kernel<<<1, 1024>>>();

    // Fused rank-assign + transpose + permute (R11-exact)
    transpose_sort_kernel<<<Ee / 32, 256>>>(x, edge_dst, w1);

    // Fused scatter + LN + ELU (R11-exact: 32 thr/node, batch-packed FFMA2)
    scatter_ln_kernel<<<(Nn + 7) / 8, 256>>>(b1, gamma, beta);

    // Fused gather + transpose + residual (R11-exact)
    gather_fused_kernel<<<Ee / GE, 256>>>(w3, b3, edge_src, x, out);
}

// round 16
// speedup vs baseline: 1.0708x; 1.0708x over previous
#include <cuda_runtime.h>
#include <cuda_fp16.h>

#define Nn 10000
#define Ee 160000
#define Cc 8
#define Bb 64
#define EPSv 1e-5f

// Scratch (device globals; allocation-free per harness rules)
__device__ __half g_xT16[Ee * Bb];     // x transposed+permuted, fp16
__device__ __half g_w1s16[Ee * Cc];    // w1 permuted, fp16 (16B per edge row)
__device__ __half g_h[Nn * Bb * Cc];   // LN+ELU activations, fp16, layout (N, B, C)
__device__ int    g_cnt[Nn];
__device__ int    g_cursor[Nn];
__device__ int    g_start[Nn + 1];

// ---------------- packed f32x2 helpers (SASS FFMA2: 2 fp32 FMAs / issue slot) ----------------

__device__ __forceinline__ unsigned long long pack2(float lo, float hi) {
    unsigned long long r;
    asm("mov.b64 %0, {%1, %2};" : "=l"(r) : "f"(lo), "f"(hi));
    return r;
}
__device__ __forceinline__ void unpack2(float& lo, float& hi, unsigned long long v) {
    asm("mov.b64 {%0, %1}, %2;" : "=f"(lo), "=f"(hi) : "l"(v));
}
__device__ __forceinline__ void fma2(unsigned long long& d,
                                     unsigned long long a, unsigned long long b) {
    asm("fma.rn.f32x2 %0, %1, %2, %3;" : "=l"(d) : "l"(a), "l"(b), "l"(d));
}

// ---------------- histogram ----------------

__global__ void hist_kernel(const int* __restrict__ dst) {
    int e = blockIdx.x * blockDim.x + threadIdx.x;
    if (e < Ee) atomicAdd(&g_cnt[dst[e]], 1);
}

// Single-block exclusive scan over N=10000 counts; also seeds g_cursor = g_start
__global__ void scan_kernel() {
    __shared__ int sh[1024];
    const int CH = (Nn + 1023) / 1024;  // 10
    int t = threadIdx.x;
    int base = t * CH;
    int loc[CH];
    int s = 0;
#pragma unroll
    for (int i = 0; i < CH; i++) {
        int v = (base + i < Nn) ? g_cnt[base + i] : 0;
        loc[i] = s;
        s += v;
    }
    sh[t] = s;
    __syncthreads();
    for (int off = 1; off < 1024; off <<= 1) {
        int v = (t >= off) ? sh[t - off] : 0;
        __syncthreads();
        if (t >= off) sh[t] += v;
        __syncthreads();
    }
    int prev = (t > 0) ? sh[t - 1] : 0;
#pragma unroll
    for (int i = 0; i < CH; i++)
        if (base + i < Nn) {
            int v = prev + loc[i];
            g_start[base + i] = v;
            g_cursor[base + i] = v;
        }
    if (t == 1023) g_start[Nn] = sh[1023];
}

// ---------------- Fused rank-assign + transpose + permute (R11-exact) ----------------

__global__ void transpose_sort_kernel(const float* __restrict__ x,
                                      const int* __restrict__ dst,
                                      const float* __restrict__ w1) {
    __shared__ float tile[32][65];   // [e_local][b]
    __shared__ int ranks[32];
    int e0 = blockIdx.x * 32;
    int t = threadIdx.x;             // 256

    if (t < 32) {
        int d = dst[e0 + t];
        ranks[t] = atomicAdd(&g_cursor[d], 1);
    }

    int tx = t & 31, ty = t >> 5;    // tx = e_local, ty = 0..7
#pragma unroll
    for (int i = 0; i < 64; i += 8)
        tile[tx][ty + i] = x[(ty + i) * Ee + e0 + tx];
    __syncthreads();

    int b = t & 63, r = t >> 6;      // r = 0..3
#pragma unroll
    for (int i = 0; i < 32; i += 4)
        g_xT16[ranks[r + i] * Bb + b] = __float2half_rn(tile[r + i][b]);

    int er = t >> 3, c = t & 7;
    g_w1s16[ranks[er] * 8 + c] = __float2half_rn(w1[e0 * 8 + t]);
}

// ---------------- Fused scatter + bias + LayerNorm + ELU (R11-exact, measured best) ----------------
// 32 threads per node, 2 batch elements per thread; fp16 streams,
// packed f32x2 accumulation (FFMA2), full fp32 precision.

__global__ void scatter_ln_kernel(const float* __restrict__ b1,
                                  const float* __restrict__ gamma,
                                  const float* __restrict__ beta) {
    int node = blockIdx.x * 8 + (threadIdx.x >> 5);
    int l    = threadIdx.x & 31;      // lane; handles b = 2l, 2l+1
    if (node >= Nn) return;

    unsigned long long acc[8];
#pragma unroll
    for (int j = 0; j < 8; j++) acc[j] = pack2(0.0f, 0.0f);

    int s  = g_start[node];
    int se = g_start[node + 1];
    int i  = s;

    for (; i + 4 <= se; i += 4) {
        __half2 xh0 = *reinterpret_cast<const __half2*>(g_xT16 + (i + 0) * Bb + 2 * l);
        __half2 xh1 = *reinterpret_cast<const __half2*>(g_xT16 + (i + 1) * Bb + 2 * l);
        __half2 xh2 = *reinterpret_cast<const __half2*>(g_xT16 + (i + 2) * Bb + 2 * l);
        __half2 xh3 = *reinterpret_cast<const __half2*>(g_xT16 + (i + 3) * Bb + 2 * l);

#pragma unroll
        for (int k = 0; k < 4; k++) {
            float2 xf = __half22float2(k == 0 ? xh0 : (k == 1 ? xh1 : (k == 2 ? xh2 : xh3)));
            unsigned long long xp = pack2(xf.x, xf.y);
            uint4 wraw = *reinterpret_cast<const uint4*>(g_w1s16 + (i + k) * 8);
            const __half2* wp = reinterpret_cast<const __half2*>(&wraw);
            float2 w01 = __half22float2(wp[0]);
            float2 w23 = __half22float2(wp[1]);
            float2 w45 = __half22float2(wp[2]);
            float2 w67 = __half22float2(wp[3]);
            fma2(acc[0], xp, pack2(w01.x, w01.x));
            fma2(acc[1], xp, pack2(w01.y, w01.y));
            fma2(acc[2], xp, pack2(w23.x, w23.x));
            fma2(acc[3], xp, pack2(w23.y, w23.y));
            fma2(acc[4], xp, pack2(w45.x, w45.x));
            fma2(acc[5], xp, pack2(w45.y, w45.y));
            fma2(acc[6], xp, pack2(w67.x, w67.x));
            fma2(acc[7], xp, pack2(w67.y, w67.y));
        }
    }
    for (; i < se; i++) {
        __half2 xh = *reinterpret_cast<const __half2*>(g_xT16 + i * Bb + 2 * l);
        float2 xf = __half22float2(xh);
        unsigned long long xp = pack2(xf.x, xf.y);
        uint4 wraw = *reinterpret_cast<const uint4*>(g_w1s16 + i * 8);
        const __half2* wp = reinterpret_cast<const __half2*>(&wraw);
        float2 w01 = __half22float2(wp[0]);
        float2 w23 = __half22float2(wp[1]);
        float2 w45 = __half22float2(wp[2]);
        float2 w67 = __half22float2(wp[3]);
        fma2(acc[0], xp, pack2(w01.x, w01.x));
        fma2(acc[1], xp, pack2(w01.y, w01.y));
        fma2(acc[2], xp, pack2(w23.x, w23.x));
        fma2(acc[3], xp, pack2(w23.y, w23.y));
        fma2(acc[4], xp, pack2(w45.x, w45.x));
        fma2(acc[5], xp, pack2(w45.y, w45.y));
        fma2(acc[6], xp, pack2(w67.x, w67.x));
        fma2(acc[7], xp, pack2(w67.y, w67.y));
    }

    // unpack accumulators: a0 = batch 2l, a1 = batch 2l+1
    float a0[8], a1[8];
#pragma unroll
    for (int j = 0; j < 8; j++) unpack2(a0[j], a1[j], acc[j]);

    float4 c0 = *reinterpret_cast<const float4*>(b1 + node * 8);
    float4 c1 = *reinterpret_cast<const float4*>(b1 + node * 8 + 4);
    float cv[8] = {c0.x, c0.y, c0.z, c0.w, c1.x, c1.y, c1.z, c1.w};
#pragma unroll
    for (int j = 0; j < 8; j++) { a0[j] += cv[j]; a1[j] += cv[j]; }

    float4 ga = *reinterpret_cast<const float4*>(gamma + node * 8);
    float4 gb = *reinterpret_cast<const float4*>(gamma + node * 8 + 4);
    float4 ba = *reinterpret_cast<const float4*>(beta  + node * 8);
    float4 bb = *reinterpret_cast<const float4*>(beta  + node * 8 + 4);
    float gv[8] = {ga.x, ga.y, ga.z, ga.w, gb.x, gb.y, gb.z, gb.w};
    float bv[8] = {ba.x, ba.y, ba.z, ba.w, bb.x, bb.y, bb.z, bb.w};

    // LayerNorm + ELU per batch element (all registers)
    __half2 hp[8];
#pragma unroll
    for (int pass = 0; pass < 2; pass++) {
        float* a = pass ? a1 : a0;
        float mu = 0.0f;
#pragma unroll
        for (int j = 0; j < 8; j++) mu += a[j];
        mu *= 0.125f;
        float var = 0.0f;
#pragma unroll
        for (int j = 0; j < 8; j++) { float d = a[j] - mu; var = fmaf(d, d, var); }
        var *= 0.125f;
        float rr = rsqrtf(var + EPSv);
        float h[8];
#pragma unroll
        for (int j = 0; j < 8; j++) {
            float v = fmaf((a[j] - mu) * rr, gv[j], bv[j]);
            h[j] = (v > 0.0f) ? v : expm1f(v);
        }
#pragma unroll
        for (int j = 0; j < 4; j++)
            hp[pass * 4 + j] = __floats2half2_rn(h[2 * j], h[2 * j + 1]);
    }

    // two 16B stores: batches 2l and 2l+1
    uint4 o0, o1;
    o0.x = *reinterpret_cast<unsigned int*>(&hp[0]);
    o0.y = *reinterpret_cast<unsigned int*>(&hp[1]);
    o0.z = *reinterpret_cast<unsigned int*>(&hp[2]);
    o0.w = *reinterpret_cast<unsigned int*>(&hp[3]);
    o1.x = *reinterpret_cast<unsigned int*>(&hp[4]);
    o1.y = *reinterpret_cast<unsigned int*>(&hp[5]);
    o1.z = *reinterpret_cast<unsigned int*>(&hp[6]);
    o1.w = *reinterpret_cast<unsigned int*>(&hp[7]);
    __half* base = g_h + node * (Bb * Cc) + (2 * l) * Cc;
    *reinterpret_cast<uint4*>(base)     = o0;
    *reinterpret_cast<uint4*>(base + 8) = o1;
}

// ---------------- Fused gather + transpose + residual via smem staging (R11-exact) ----------------

#define GE 64  // edges per block

__global__ void gather_fused_kernel(const float* __restrict__ w3,
                                    const float* __restrict__ b3,
                                    const int* __restrict__ src,
                                    const float* __restrict__ x,
                                    float* __restrict__ out) {
    __shared__ float tile[Bb][GE + 1];
    int e0 = blockIdx.x * GE;
    int t = threadIdx.x;          // 256
    int b = t & 63;
    int g = t >> 6;               // 0..3

#pragma unroll 4
    for (int i = g; i < GE; i += 4) {
        int e = e0 + i;
        int sn = __ldg(src + e);                   // uniform within group
        uint4 raw = *reinterpret_cast<const uint4*>(g_h + sn * (Bb * Cc) + b * Cc);
        float2 f0 = __half22float2(*reinterpret_cast<__half2*>(&raw.x));
        float2 f1 = __half22float2(*reinterpret_cast<__half2*>(&raw.y));
        float2 f2 = __half22float2(*reinterpret_cast<__half2*>(&raw.z));
        float2 f3 = __half22float2(*reinterpret_cast<__half2*>(&raw.w));
        float4 wa = *reinterpret_cast<const float4*>(w3 + e * 8);
        float4 wb = *reinterpret_cast<const float4*>(w3 + e * 8 + 4);
        float sum = __ldg(b3 + e);
        sum = fmaf(f0.x, wa.x, sum);
        sum = fmaf(f0.y, wa.y, sum);
        sum = fmaf(f1.x, wa.z, sum);
        sum = fmaf(f1.y, wa.w, sum);
        sum = fmaf(f2.x, wb.x, sum);
        sum = fmaf(f2.y, wb.y, sum);
        sum = fmaf(f3.x, wb.z, sum);
        sum = fmaf(f3.y, wb.w, sum);
        tile[b][i] = sum;                          // stride-65: conflict-free
    }
    __syncthreads();

    int el = t & 63;
#pragma unroll
    for (int k = 0; k < 16; k++) {
        int b2 = (t >> 6) + k * 4;
        int idx = b2 * Ee + e0 + el;
        __stcs(&out[idx], tile[b2][el] + x[idx]);
    }
}

// ---------------- Launch ----------------

extern "C" void kernel_launch(void* const* d_in, const int* in_sizes, int n_in,
                              void* d_out, int out_size) {
    const float* x     = (const float*)d_in[0];   // (B,E)
    const float* w1    = (const float*)d_in[1];   // (E,C)
    const float* b1    = (const float*)d_in[2];   // (N,C)
    const float* gamma = (const float*)d_in[3];   // (N,C)
    const float* beta  = (const float*)d_in[4];   // (N,C)
    const float* w3    = (const float*)d_in[5];   // (E,C)
    const float* b3    = (const float*)d_in[6];   // (E,)
    const int* edge_src = (const int*)d_in[7];    // (E,)
    const int* edge_dst = (const int*)d_in[8];    // (E,)
    float* out = (float*)d_out;                   // (B,E)

    // Zero histogram
    void* cnt_ptr = nullptr;
    cudaGetSymbolAddress(&cnt_ptr, g_cnt);
    cudaMemsetAsync(cnt_ptr, 0, Nn * sizeof(int));

    hist_kernel<<<(Ee + 255) / 256, 256>>>(edge_dst);
    scan_kernel<<<1, 1024>>>();

    // Fused rank-assign + transpose + permute (fp16 outputs)
    transpose_sort_kernel<<<Ee / 32, 256>>>(x, edge_dst, w1);

    // Fused scatter + LN + ELU (32 thr/node, f32x2 packed FMA)
    scatter_ln_kernel<<<(Nn + 7) / 8, 256>>>(b1, gamma, beta);

    // Fused gather + transpose + residual
    gather_fused_kernel<<<Ee / GE, 256>>>(w3, b3, edge_src, x, out);
}

// round 17
// speedup vs baseline: 1.1335x; 1.0585x over previous
#include <cuda_runtime.h>
#include <cuda_fp16.h>

#define Nn 10000
#define Ee 160000
#define Cc 8
#define Bb 64
#define EPSv 1e-5f

// Scratch (device globals; allocation-free per harness rules)
__device__ __half g_xT16[Ee * Bb];     // x transposed+permuted, fp16
__device__ __half g_w1s16[Ee * Cc];    // w1 permuted, fp16 (16B per edge row)
__device__ __half g_h[Nn * Bb * Cc];   // LN+ELU activations, fp16, layout (N, B, C)
__device__ int    g_cnt[Nn];
__device__ int    g_lrank[Ee];         // local rank of edge within its dst node (from hist atomic)
__device__ int    g_start[Nn + 1];

// ---------------- packed f32x2 helpers (SASS FFMA2: 2 fp32 FMAs / issue slot) ----------------

__device__ __forceinline__ unsigned long long pack2(float lo, float hi) {
    unsigned long long r;
    asm("mov.b64 %0, {%1, %2};" : "=l"(r) : "f"(lo), "f"(hi));
    return r;
}
__device__ __forceinline__ void unpack2(float& lo, float& hi, unsigned long long v) {
    asm("mov.b64 {%0, %1}, %2;" : "=f"(lo), "=f"(hi) : "l"(v));
}
__device__ __forceinline__ void fma2(unsigned long long& d,
                                     unsigned long long a, unsigned long long b) {
    asm("fma.rn.f32x2 %0, %1, %2, %3;" : "=l"(d) : "l"(a), "l"(b), "l"(d));
}

// ---------------- histogram (also records each edge's local rank) ----------------

__global__ void hist_kernel(const int* __restrict__ dst) {
    int e = blockIdx.x * blockDim.x + threadIdx.x;
    if (e < Ee) g_lrank[e] = atomicAdd(&g_cnt[dst[e]], 1);
}

// Single-block exclusive scan over N=10000 counts -> g_start only
__global__ void scan_kernel() {
    __shared__ int sh[1024];
    const int CH = (Nn + 1023) / 1024;  // 10
    int t = threadIdx.x;
    int base = t * CH;
    int loc[CH];
    int s = 0;
#pragma unroll
    for (int i = 0; i < CH; i++) {
        int v = (base + i < Nn) ? g_cnt[base + i] : 0;
        loc[i] = s;
        s += v;
    }
    sh[t] = s;
    __syncthreads();
    for (int off = 1; off < 1024; off <<= 1) {
        int v = (t >= off) ? sh[t - off] : 0;
        __syncthreads();
        if (t >= off) sh[t] += v;
        __syncthreads();
    }
    int prev = (t > 0) ? sh[t - 1] : 0;
#pragma unroll
    for (int i = 0; i < CH; i++)
        if (base + i < Nn) g_start[base + i] = prev + loc[i];
    if (t == 1023) g_start[Nn] = sh[1023];
}

// ---------------- Fused transpose + permute (atomic-free rank lookup) ----------------

__global__ void transpose_sort_kernel(const float* __restrict__ x,
                                      const int* __restrict__ dst,
                                      const float* __restrict__ w1) {
    __shared__ float tile[32][65];   // [e_local][b]
    __shared__ int ranks[32];
    int e0 = blockIdx.x * 32;
    int t = threadIdx.x;             // 256

    // warp 0: rank = start[dst[e]] + lrank[e]  (plain loads, no atomics)
    if (t < 32) {
        int d = dst[e0 + t];
        ranks[t] = g_start[d] + g_lrank[e0 + t];
    }

    int tx = t & 31, ty = t >> 5;    // tx = e_local, ty = 0..7
#pragma unroll
    for (int i = 0; i < 64; i += 8)
        tile[tx][ty + i] = x[(ty + i) * Ee + e0 + tx];
    __syncthreads();

    int b = t & 63, r = t >> 6;      // r = 0..3
#pragma unroll
    for (int i = 0; i < 32; i += 4)
        g_xT16[ranks[r + i] * Bb + b] = __float2half_rn(tile[r + i][b]);

    int er = t >> 3, c = t & 7;
    g_w1s16[ranks[er] * 8 + c] = __float2half_rn(w1[e0 * 8 + t]);
}

// ---------------- Fused scatter + bias + LayerNorm + ELU (R11 body + occupancy cap) ----------------
// 32 threads per node, 2 batch elements per thread; fp16 streams,
// packed f32x2 accumulation (FFMA2), full fp32 precision.

__global__ void __launch_bounds__(256, 5)
scatter_ln_kernel(const float* __restrict__ b1,
                  const float* __restrict__ gamma,
                  const float* __restrict__ beta) {
    int node = blockIdx.x * 8 + (threadIdx.x >> 5);
    int l    = threadIdx.x & 31;      // lane; handles b = 2l, 2l+1
    if (node >= Nn) return;

    unsigned long long acc[8];
#pragma unroll
    for (int j = 0; j < 8; j++) acc[j] = pack2(0.0f, 0.0f);

    int s  = g_start[node];
    int se = g_start[node + 1];
    int i  = s;

    for (; i + 4 <= se; i += 4) {
        __half2 xh0 = *reinterpret_cast<const __half2*>(g_xT16 + (i + 0) * Bb + 2 * l);
        __half2 xh1 = *reinterpret_cast<const __half2*>(g_xT16 + (i + 1) * Bb + 2 * l);
        __half2 xh2 = *reinterpret_cast<const __half2*>(g_xT16 + (i + 2) * Bb + 2 * l);
        __half2 xh3 = *reinterpret_cast<const __half2*>(g_xT16 + (i + 3) * Bb + 2 * l);

#pragma unroll
        for (int k = 0; k < 4; k++) {
            float2 xf = __half22float2(k == 0 ? xh0 : (k == 1 ? xh1 : (k == 2 ? xh2 : xh3)));
            unsigned long long xp = pack2(xf.x, xf.y);
            uint4 wraw = *reinterpret_cast<const uint4*>(g_w1s16 + (i + k) * 8);
            const __half2* wp = reinterpret_cast<const __half2*>(&wraw);
            float2 w01 = __half22float2(wp[0]);
            float2 w23 = __half22float2(wp[1]);
            float2 w45 = __half22float2(wp[2]);
            float2 w67 = __half22float2(wp[3]);
            fma2(acc[0], xp, pack2(w01.x, w01.x));
            fma2(acc[1], xp, pack2(w01.y, w01.y));
            fma2(acc[2], xp, pack2(w23.x, w23.x));
            fma2(acc[3], xp, pack2(w23.y, w23.y));
            fma2(acc[4], xp, pack2(w45.x, w45.x));
            fma2(acc[5], xp, pack2(w45.y, w45.y));
            fma2(acc[6], xp, pack2(w67.x, w67.x));
            fma2(acc[7], xp, pack2(w67.y, w67.y));
        }
    }
    for (; i < se; i++) {
        __half2 xh = *reinterpret_cast<const __half2*>(g_xT16 + i * Bb + 2 * l);
        float2 xf = __half22float2(xh);
        unsigned long long xp = pack2(xf.x, xf.y);
        uint4 wraw = *reinterpret_cast<const uint4*>(g_w1s16 + i * 8);
        const __half2* wp = reinterpret_cast<const __half2*>(&wraw);
        float2 w01 = __half22float2(wp[0]);
        float2 w23 = __half22float2(wp[1]);
        float2 w45 = __half22float2(wp[2]);
        float2 w67 = __half22float2(wp[3]);
        fma2(acc[0], xp, pack2(w01.x, w01.x));
        fma2(acc[1], xp, pack2(w01.y, w01.y));
        fma2(acc[2], xp, pack2(w23.x, w23.x));
        fma2(acc[3], xp, pack2(w23.y, w23.y));
        fma2(acc[4], xp, pack2(w45.x, w45.x));
        fma2(acc[5], xp, pack2(w45.y, w45.y));
        fma2(acc[6], xp, pack2(w67.x, w67.x));
        fma2(acc[7], xp, pack2(w67.y, w67.y));
    }

    // unpack accumulators: a0 = batch 2l, a1 = batch 2l+1
    float a0[8], a1[8];
#pragma unroll
    for (int j = 0; j < 8; j++) unpack2(a0[j], a1[j], acc[j]);

    float4 c0 = *reinterpret_cast<const float4*>(b1 + node * 8);
    float4 c1 = *reinterpret_cast<const float4*>(b1 + node * 8 + 4);
    float cv[8] = {c0.x, c0.y, c0.z, c0.w, c1.x, c1.y, c1.z, c1.w};
#pragma unroll
    for (int j = 0; j < 8; j++) { a0[j] += cv[j]; a1[j] += cv[j]; }

    float4 ga = *reinterpret_cast<const float4*>(gamma + node * 8);
    float4 gb = *reinterpret_cast<const float4*>(gamma + node * 8 + 4);
    float4 ba = *reinterpret_cast<const float4*>(beta  + node * 8);
    float4 bb = *reinterpret_cast<const float4*>(beta  + node * 8 + 4);
    float gv[8] = {ga.x, ga.y, ga.z, ga.w, gb.x, gb.y, gb.z, gb.w};
    float bv[8] = {ba.x, ba.y, ba.z, ba.w, bb.x, bb.y, bb.z, bb.w};

    // LayerNorm + ELU per batch element (all registers)
    __half2 hp[8];
#pragma unroll
    for (int pass = 0; pass < 2; pass++) {
        float* a = pass ? a1 : a0;
        float mu = 0.0f;
#pragma unroll
        for (int j = 0; j < 8; j++) mu += a[j];
        mu *= 0.125f;
        float var = 0.0f;
#pragma unroll
        for (int j = 0; j < 8; j++) { float d = a[j] - mu; var = fmaf(d, d, var); }
        var *= 0.125f;
        float rr = rsqrtf(var + EPSv);
        float h[8];
#pragma unroll
        for (int j = 0; j < 8; j++) {
            float v = fmaf((a[j] - mu) * rr, gv[j], bv[j]);
            h[j] = (v > 0.0f) ? v : expm1f(v);
        }
#pragma unroll
        for (int j = 0; j < 4; j++)
            hp[pass * 4 + j] = __floats2half2_rn(h[2 * j], h[2 * j + 1]);
    }

    // two 16B stores: batches 2l and 2l+1
    uint4 o0, o1;
    o0.x = *reinterpret_cast<unsigned int*>(&hp[0]);
    o0.y = *reinterpret_cast<unsigned int*>(&hp[1]);
    o0.z = *reinterpret_cast<unsigned int*>(&hp[2]);
    o0.w = *reinterpret_cast<unsigned int*>(&hp[3]);
    o1.x = *reinterpret_cast<unsigned int*>(&hp[4]);
    o1.y = *reinterpret_cast<unsigned int*>(&hp[5]);
    o1.z = *reinterpret_cast<unsigned int*>(&hp[6]);
    o1.w = *reinterpret_cast<unsigned int*>(&hp[7]);
    __half* base = g_h + node * (Bb * Cc) + (2 * l) * Cc;
    *reinterpret_cast<uint4*>(base)     = o0;
    *reinterpret_cast<uint4*>(base + 8) = o1;
}

// ---------------- Fused gather + transpose + residual via smem staging (R11-exact) ----------------

#define GE 64  // edges per block

__global__ void gather_fused_kernel(const float* __restrict__ w3,
                                    const float* __restrict__ b3,
                                    const int* __restrict__ src,
                                    const float* __restrict__ x,
                                    float* __restrict__ out) {
    __shared__ float tile[Bb][GE + 1];
    int e0 = blockIdx.x * GE;
    int t = threadIdx.x;          // 256
    int b = t & 63;
    int g = t >> 6;               // 0..3

#pragma unroll 4
    for (int i = g; i < GE; i += 4) {
        int e = e0 + i;
        int sn = __ldg(src + e);                   // uniform within group
        uint4 raw = *reinterpret_cast<const uint4*>(g_h + sn * (Bb * Cc) + b * Cc);
        float2 f0 = __half22float2(*reinterpret_cast<__half2*>(&raw.x));
        float2 f1 = __half22float2(*reinterpret_cast<__half2*>(&raw.y));
        float2 f2 = __half22float2(*reinterpret_cast<__half2*>(&raw.z));
        float2 f3 = __half22float2(*reinterpret_cast<__half2*>(&raw.w));
        float4 wa = *reinterpret_cast<const float4*>(w3 + e * 8);
        float4 wb = *reinterpret_cast<const float4*>(w3 + e * 8 + 4);
        float sum = __ldg(b3 + e);
        sum = fmaf(f0.x, wa.x, sum);
        sum = fmaf(f0.y, wa.y, sum);
        sum = fmaf(f1.x, wa.z, sum);
        sum = fmaf(f1.y, wa.w, sum);
        sum = fmaf(f2.x, wb.x, sum);
        sum = fmaf(f2.y, wb.y, sum);
        sum = fmaf(f3.x, wb.z, sum);
        sum = fmaf(f3.y, wb.w, sum);
        tile[b][i] = sum;                          // stride-65: conflict-free
    }
    __syncthreads();

    int el = t & 63;
#pragma unroll
    for (int k = 0; k < 16; k++) {
        int b2 = (t >> 6) + k * 4;
        int idx = b2 * Ee + e0 + el;
        __stcs(&out[idx], tile[b2][el] + x[idx]);
    }
}

// ---------------- Launch ----------------

extern "C" void kernel_launch(void* const* d_in, const int* in_sizes, int n_in,
                              void* d_out, int out_size) {
    const float* x     = (const float*)d_in[0];   // (B,E)
    const float* w1    = (const float*)d_in[1];   // (E,C)
    const float* b1    = (const float*)d_in[2];   // (N,C)
    const float* gamma = (const float*)d_in[3];   // (N,C)
    const float* beta  = (const float*)d_in[4];   // (N,C)
    const float* w3    = (const float*)d_in[5];   // (E,C)
    const float* b3    = (const float*)d_in[6];   // (E,)
    const int* edge_src = (const int*)d_in[7];    // (E,)
    const int* edge_dst = (const int*)d_in[8];    // (E,)
    float* out = (float*)d_out;                   // (B,E)

    // Zero histogram
    void* cnt_ptr = nullptr;
    cudaGetSymbolAddress(&cnt_ptr, g_cnt);
    cudaMemsetAsync(cnt_ptr, 0, Nn * sizeof(int));

    hist_kernel<<<(Ee + 255) / 256, 256>>>(edge_dst);
    scan_kernel<<<1, 1024>>>();

    // Fused transpose + permute (rank = start + lrank; no atomics)
    transpose_sort_kernel<<<Ee / 32, 256>>>(x, edge_dst, w1);

    // Fused scatter + LN + ELU (32 thr/node, f32x2 packed FMA, occ-capped)
    scatter_ln_kernel<<<(Nn + 7) / 8, 256>>>(b1, gamma, beta);

    // Fused gather + transpose + residual
    gather_fused_kernel<<<Ee / GE, 256>>>(w3, b3, edge_src, x, out);
}